// round 7
// baseline (speedup 1.0000x reference)
#include <cuda_runtime.h>
#include <cuda_bf16.h>

// Problem constants (fixed by dataset)
#define NSRC_MAX 10000
#define NDST_MAX 10000
#define EDGE_MAX 640000
#define SDIM 128
#define HNUM 4
#define DDIM 32

typedef unsigned long long u64;
typedef unsigned int u32;

// ---------------- device scratch (static, no allocs) ----------------
__device__ u32   g_ub[NSRC_MAX * (SDIM / 2)];   // x_src @ W_res^T as bf16x2 pairs
__device__ float g_v[NDST_MAX * SDIM];          // pred  @ W_res^T
__device__ float g_t1[NDST_MAX * SDIM];         // relu(x_dst @ W_pred1^T + b1)
__device__ float g_as[NSRC_MAX * HNUM];
__device__ float g_ad[NDST_MAX * HNUM];
__device__ float g_Msrc[SDIM * HNUM];
__device__ float g_Mdst[SDIM * HNUM];
__device__ float g_Wrv[SDIM * SDIM];            // W_res @ W_pred2
__device__ float g_brv[SDIM];                   // W_res @ b_pred2
__device__ int   g_cnt[NDST_MAX + 1];
__device__ int   g_off[NDST_MAX + 1];
__device__ int   g_cur[NDST_MAX];
__device__ int   g_csr_src[EDGE_MAX];

__device__ __forceinline__ float warp_sum(float v) {
    #pragma unroll
    for (int o = 16; o; o >>= 1) v += __shfl_xor_sync(0xffffffffu, v, o);
    return v;
}

// ---- f32x2 packed-math helpers (FFMA2: PTX-only, doubles fp32 FMA rate) ----
__device__ __forceinline__ u64 pack2(float x, float y) {
    u64 r;
    asm("mov.b64 %0, {%1, %2};" : "=l"(r)
        : "r"(__float_as_uint(x)), "r"(__float_as_uint(y)));
    return r;
}
__device__ __forceinline__ float2 unpack2(u64 v) {
    u32 lo, hi;
    asm("mov.b64 {%0, %1}, %2;" : "=r"(lo), "=r"(hi) : "l"(v));
    return make_float2(__uint_as_float(lo), __uint_as_float(hi));
}
__device__ __forceinline__ void fma2(u64& d, u64 a, u64 b) {
    asm("fma.rn.f32x2 %0, %1, %2, %3;" : "=l"(d) : "l"(a), "l"(b), "l"(d));
}
// pack (lo, hi) floats to bf16x2 (first PTX source -> upper half)
__device__ __forceinline__ u32 bf2(float lo, float hi) {
    u32 r;
    asm("cvt.rn.bf16x2.f32 %0, %1, %2;" : "=r"(r) : "f"(hi), "f"(lo));
    return r;
}

// ---------------- tiny precompute kernels ----------------
// Fold attention vectors into weights: M[s,h] = sum_d W[(h*32+d)*128 + s] * att[h*32+d]
__global__ void k_fold_att(const float* __restrict__ Wsrc, const float* __restrict__ attsrc,
                           const float* __restrict__ Wdst, const float* __restrict__ attdst) {
    int b = blockIdx.x;
    const float* W   = b ? Wdst   : Wsrc;
    const float* att = b ? attdst : attsrc;
    float* out       = b ? g_Mdst : g_Msrc;
    int t = threadIdx.x;
    if (t >= SDIM * HNUM) return;
    int s = t >> 2, h = t & 3;
    float acc = 0.f;
    #pragma unroll 8
    for (int d = 0; d < DDIM; d++)
        acc += W[(h * DDIM + d) * SDIM + s] * att[h * DDIM + d];
    out[s * 4 + h] = acc;
}

// W_rv[o,k] = sum_i W_res[o,i] * W_pred2[i,k];  b_rv[o] = sum_i W_res[o,i] * b_pred2[i]
__global__ void k_wrv(const float* __restrict__ Wres, const float* __restrict__ Wpred2,
                      const float* __restrict__ bpred2) {
    __shared__ float sh[SDIM];
    __shared__ float ws[4];
    int o = blockIdx.x, t = threadIdx.x;
    sh[t] = Wres[o * SDIM + t];
    __syncthreads();
    float s = 0.f;
    #pragma unroll 8
    for (int i = 0; i < SDIM; i++)
        s += sh[i] * Wpred2[i * SDIM + t];
    g_Wrv[o * SDIM + t] = s;
    float p = sh[t] * bpred2[t];
    p = warp_sum(p);
    if ((t & 31) == 0) ws[t >> 5] = p;
    __syncthreads();
    if (t == 0) g_brv[o] = ws[0] + ws[1] + ws[2] + ws[3];
}

// a[n,h] = sum_k x[n,k] * M[k,h]   (warp per row)
__global__ void k_logits(const float* __restrict__ xsrc, const float* __restrict__ xdst,
                         int Nsrc, int Ndst) {
    int y = blockIdx.y;
    const float* x  = y ? xdst   : xsrc;
    const float* Mw = y ? g_Mdst : g_Msrc;
    float* out      = y ? g_ad   : g_as;
    int N           = y ? Ndst   : Nsrc;
    int warp = threadIdx.x >> 5, lane = threadIdx.x & 31;
    int row = blockIdx.x * 8 + warp;
    if (row >= N) return;
    const float* xr = x + row * SDIM;
    float p0 = 0, p1 = 0, p2 = 0, p3 = 0;
    #pragma unroll
    for (int k = lane; k < SDIM; k += 32) {
        float xv = __ldg(&xr[k]);
        p0 += xv * Mw[k * 4 + 0];
        p1 += xv * Mw[k * 4 + 1];
        p2 += xv * Mw[k * 4 + 2];
        p3 += xv * Mw[k * 4 + 3];
    }
    p0 = warp_sum(p0); p1 = warp_sum(p1); p2 = warp_sum(p2); p3 = warp_sum(p3);
    if (lane == 0) {
        out[row * 4 + 0] = p0; out[row * 4 + 1] = p1;
        out[row * 4 + 2] = p2; out[row * 4 + 3] = p3;
    }
}

// ---------------- GEMM: C[M,128] = act(A[M,128] @ B[128,128]^T + bias) ----------------
// 128x128 tile, 256 threads, 8x8 per thread via f32x2 packed FMA.
// flags: bit0 = relu, bit1 = bf16 output into g_ub (C ignored)
#define TM 128
#define TN 128
#define TK 16
__global__ __launch_bounds__(256) void k_gemm1(
    const float* __restrict__ A, const float* __restrict__ B,
    const float* __restrict__ bias, float* __restrict__ C,
    int M, int flags) {

    int doRelu = flags & 1, toBf16 = flags & 2;

    __shared__ float As[TK][TM + 4];
    __shared__ float Bs[TK][TN + 4];

    int tid = threadIdx.x;
    int tx = tid & 15, ty = tid >> 4;
    int row0 = blockIdx.x * TM;
    if (row0 >= M) return;

    u64 acc[8][4];
    #pragma unroll
    for (int r = 0; r < 8; r++)
        #pragma unroll
        for (int c = 0; c < 4; c++) acc[r][c] = 0ull;

    for (int k0 = 0; k0 < SDIM; k0 += TK) {
        // A tile: 128 rows x 16 k = 512 float4 loads (2 per thread)
        #pragma unroll
        for (int i = 0; i < 2; i++) {
            int idx = tid + 256 * i;
            int r = idx >> 2, q = idx & 3;
            int grow = row0 + r;
            float4 vv = make_float4(0.f, 0.f, 0.f, 0.f);
            if (grow < M)
                vv = *reinterpret_cast<const float4*>(&A[grow * SDIM + k0 + q * 4]);
            As[q * 4 + 0][r] = vv.x; As[q * 4 + 1][r] = vv.y;
            As[q * 4 + 2][r] = vv.z; As[q * 4 + 3][r] = vv.w;
        }
        // B tile: 128 n x 16 k
        #pragma unroll
        for (int i = 0; i < 2; i++) {
            int idx = tid + 256 * i;
            int n = idx >> 2, q = idx & 3;
            float4 vv = *reinterpret_cast<const float4*>(&B[n * SDIM + k0 + q * 4]);
            Bs[q * 4 + 0][n] = vv.x; Bs[q * 4 + 1][n] = vv.y;
            Bs[q * 4 + 2][n] = vv.z; Bs[q * 4 + 3][n] = vv.w;
        }
        __syncthreads();
        #pragma unroll
        for (int kk = 0; kk < TK; kk++) {
            float4 aL = *reinterpret_cast<const float4*>(&As[kk][ty * 4]);
            float4 aH = *reinterpret_cast<const float4*>(&As[kk][ty * 4 + 64]);
            float4 bL = *reinterpret_cast<const float4*>(&Bs[kk][tx * 4]);
            float4 bH = *reinterpret_cast<const float4*>(&Bs[kk][tx * 4 + 64]);
            u64 a2[8];
            a2[0] = pack2(aL.x, aL.x); a2[1] = pack2(aL.y, aL.y);
            a2[2] = pack2(aL.z, aL.z); a2[3] = pack2(aL.w, aL.w);
            a2[4] = pack2(aH.x, aH.x); a2[5] = pack2(aH.y, aH.y);
            a2[6] = pack2(aH.z, aH.z); a2[7] = pack2(aH.w, aH.w);
            u64 b2[4];
            b2[0] = pack2(bL.x, bL.y); b2[1] = pack2(bL.z, bL.w);
            b2[2] = pack2(bH.x, bH.y); b2[3] = pack2(bH.z, bH.w);
            #pragma unroll
            for (int r = 0; r < 8; r++)
                #pragma unroll
                for (int c = 0; c < 4; c++)
                    fma2(acc[r][c], a2[r], b2[c]);
        }
        __syncthreads();
    }

    // epilogue: columns tx*4..tx*4+3 (lo) and 64+tx*4..+3 (hi)
    float4 bsL = make_float4(0.f, 0.f, 0.f, 0.f), bsH = bsL;
    if (bias) {
        bsL = *reinterpret_cast<const float4*>(&bias[tx * 4]);
        bsH = *reinterpret_cast<const float4*>(&bias[64 + tx * 4]);
    }
    #pragma unroll
    for (int r = 0; r < 8; r++) {
        int grow = row0 + ((r < 4) ? (ty * 4 + r) : (64 + ty * 4 + r - 4));
        if (grow >= M) continue;
        float2 p0 = unpack2(acc[r][0]), p1 = unpack2(acc[r][1]);
        float2 p2 = unpack2(acc[r][2]), p3 = unpack2(acc[r][3]);
        float4 lo = make_float4(p0.x + bsL.x, p0.y + bsL.y, p1.x + bsL.z, p1.y + bsL.w);
        float4 hi = make_float4(p2.x + bsH.x, p2.y + bsH.y, p3.x + bsH.z, p3.y + bsH.w);
        if (doRelu) {
            lo.x = fmaxf(lo.x, 0.f); lo.y = fmaxf(lo.y, 0.f);
            lo.z = fmaxf(lo.z, 0.f); lo.w = fmaxf(lo.w, 0.f);
            hi.x = fmaxf(hi.x, 0.f); hi.y = fmaxf(hi.y, 0.f);
            hi.z = fmaxf(hi.z, 0.f); hi.w = fmaxf(hi.w, 0.f);
        }
        if (toBf16) {
            uint2 uL = make_uint2(bf2(lo.x, lo.y), bf2(lo.z, lo.w));
            uint2 uH = make_uint2(bf2(hi.x, hi.y), bf2(hi.z, hi.w));
            *reinterpret_cast<uint2*>(&g_ub[grow * (SDIM / 2) + tx * 2]) = uL;
            *reinterpret_cast<uint2*>(&g_ub[grow * (SDIM / 2) + 32 + tx * 2]) = uH;
        } else {
            *reinterpret_cast<float4*>(&C[grow * SDIM + tx * 4]) = lo;
            *reinterpret_cast<float4*>(&C[grow * SDIM + 64 + tx * 4]) = hi;
        }
    }
}

// ---------------- CSR build (4 edges / thread for atomic-latency overlap) ----------------
__global__ void k_count(const int* __restrict__ edst, int E) {
    int i = blockIdx.x * blockDim.x + threadIdx.x;
    int n4 = E >> 2;
    if (i < n4) {
        int4 d = reinterpret_cast<const int4*>(edst)[i];
        atomicAdd(&g_cnt[d.x], 1);
        atomicAdd(&g_cnt[d.y], 1);
        atomicAdd(&g_cnt[d.z], 1);
        atomicAdd(&g_cnt[d.w], 1);
    } else if (i == n4) {
        for (int j = n4 * 4; j < E; j++) atomicAdd(&g_cnt[edst[j]], 1);
    }
}

__global__ void k_scan(int N) {
    __shared__ int sh[1024];
    int t = threadIdx.x;
    int per = (N + 1023) >> 10;
    int s = t * per, e = min(N, s + per);
    int tot = 0;
    for (int i = s; i < e; i++) tot += g_cnt[i];
    sh[t] = tot;
    __syncthreads();
    for (int o = 1; o < 1024; o <<= 1) {
        int v = (t >= o) ? sh[t - o] : 0;
        __syncthreads();
        sh[t] += v;
        __syncthreads();
    }
    int run = (t == 0) ? 0 : sh[t - 1];
    for (int i = s; i < e; i++) {
        g_off[i] = run;
        g_cur[i] = run;
        run += g_cnt[i];
    }
    if (t == 1023) g_off[N] = sh[1023];
}

__global__ void k_scatter(const int* __restrict__ esrc, const int* __restrict__ edst, int E) {
    int i = blockIdx.x * blockDim.x + threadIdx.x;
    int n4 = E >> 2;
    if (i < n4) {
        int4 d = reinterpret_cast<const int4*>(edst)[i];
        int4 s = reinterpret_cast<const int4*>(esrc)[i];
        int p0 = atomicAdd(&g_cur[d.x], 1);
        int p1 = atomicAdd(&g_cur[d.y], 1);
        int p2 = atomicAdd(&g_cur[d.z], 1);
        int p3 = atomicAdd(&g_cur[d.w], 1);
        g_csr_src[p0] = s.x;
        g_csr_src[p1] = s.y;
        g_csr_src[p2] = s.z;
        g_csr_src[p3] = s.w;
    } else if (i == n4) {
        for (int j = n4 * 4; j < E; j++) {
            int p = atomicAdd(&g_cur[edst[j]], 1);
            g_csr_src[p] = esrc[j];
        }
    }
}

// ---------------- edge aggregation: one block (128 thr) per dst node ----------------
#define CAP 512
__global__ __launch_bounds__(128) void k_edge(float* __restrict__ dout) {
    __shared__ int    sh_src[CAP];
    __shared__ float  sh_ex[4][CAP];
    __shared__ float  sh_denom[4];
    __shared__ float2 red[64];

    int d = blockIdx.x;
    int t = threadIdx.x;
    int start = g_off[d], end = g_off[d + 1];
    int n = end - start;

    // pass 1: warp h1 computes exp-weights for head h1; warp 0 also caches src ids
    int h1 = t >> 5, lane = t & 31;
    float adh1 = g_ad[d * 4 + h1];
    float part = 0.f;
    for (int i = lane; i < n; i += 32) {
        int src = g_csr_src[start + i];
        if (h1 == 0 && i < CAP) sh_src[i] = src;
        float z = g_as[src * 4 + h1] + adh1;
        z = fmaxf(z, 0.f) + 0.2f * fminf(z, 0.f);   // leaky_relu 0.2
        float ex = __expf(z);                        // softmax shift-invariant: skip amax
        if (i < CAP) sh_ex[h1][i] = ex;
        part += ex;
    }
    part = warp_sum(part);
    if (lane == 0) sh_denom[h1] = part;
    __syncthreads();

    // pass 2: 64 channel-pairs x 2 edge-slots; bf16x2 u loads
    int p = t & 63, slot = t >> 6;
    int h2 = p >> 4;                     // head of channels 2p, 2p+1
    float denom = sh_denom[h2];
    float inv = 1.f / (denom + 1e-16f);
    float sumw = denom * inv;

    float ax = 0.f, ay = 0.f;
    int ncap = n < CAP ? n : CAP;
    #pragma unroll 4
    for (int i = slot; i < ncap; i += 2) {
        int src = sh_src[i];
        float w = sh_ex[h2][i];
        u32 uv = __ldg(&g_ub[src * (SDIM / 2) + p]);
        float ux = __uint_as_float(uv << 16);
        float uy = __uint_as_float(uv & 0xffff0000u);
        ax += w * ux;
        ay += w * uy;
    }
    // overflow path (n > CAP): recompute weights on the fly (rare/never for this data)
    if (n > CAP) {
        float adh2 = g_ad[d * 4 + h2];
        for (int j = CAP + slot; j < n; j += 2) {
            int src = g_csr_src[start + j];
            float z = g_as[src * 4 + h2] + adh2;
            z = fmaxf(z, 0.f) + 0.2f * fminf(z, 0.f);
            float w = __expf(z);
            u32 uv = __ldg(&g_ub[src * (SDIM / 2) + p]);
            ax += w * __uint_as_float(uv << 16);
            ay += w * __uint_as_float(uv & 0xffff0000u);
        }
    }

    if (slot == 1) red[p] = make_float2(ax, ay);
    __syncthreads();
    if (slot == 0) {
        ax += red[p].x;
        ay += red[p].y;
        float2 vv = *reinterpret_cast<const float2*>(&g_v[d * SDIM + 2 * p]);
        float2 oo = *reinterpret_cast<const float2*>(&dout[d * SDIM + 2 * p]);
        oo.x += ax * inv - vv.x * sumw;
        oo.y += ay * inv - vv.y * sumw;
        *reinterpret_cast<float2*>(&dout[d * SDIM + 2 * p]) = oo;
    }
}

// ---------------- launch: 5-way parallel DAG ----------------
extern "C" void kernel_launch(void* const* d_in, const int* in_sizes, int n_in,
                              void* d_out, int out_size) {
    const float* x_src   = (const float*)d_in[0];
    const float* x_dst   = (const float*)d_in[1];
    const float* W_pred1 = (const float*)d_in[2];
    const float* b_pred1 = (const float*)d_in[3];
    const float* W_pred2 = (const float*)d_in[4];
    const float* b_pred2 = (const float*)d_in[5];
    const float* W_res   = (const float*)d_in[6];
    const float* W_src   = (const float*)d_in[7];
    const float* W_dst   = (const float*)d_in[8];
    const float* att_src = (const float*)d_in[9];
    const float* att_dst = (const float*)d_in[10];
    const float* W_self  = (const float*)d_in[11];
    const float* b_self  = (const float*)d_in[12];
    const int*   e_src   = (const int*)d_in[13];
    const int*   e_dst   = (const int*)d_in[14];
    float* out = (float*)d_out;

    int Nsrc = in_sizes[0] / SDIM;
    int Ndst = in_sizes[1] / SDIM;
    int E    = in_sizes[13];
    int maxN = Nsrc > Ndst ? Nsrc : Ndst;

    void* cnt_ptr = nullptr;
    cudaGetSymbolAddress(&cnt_ptr, g_cnt);
    float* t1_ptr = nullptr;  float* v_ptr = nullptr;
    float* wrv_ptr = nullptr; float* brv_ptr = nullptr;
    cudaGetSymbolAddress((void**)&t1_ptr, g_t1);
    cudaGetSymbolAddress((void**)&v_ptr, g_v);
    cudaGetSymbolAddress((void**)&wrv_ptr, g_Wrv);
    cudaGetSymbolAddress((void**)&brv_ptr, g_brv);

    cudaStream_t sA, sB, sC, sD;
    cudaStreamCreateWithFlags(&sA, cudaStreamNonBlocking);
    cudaStreamCreateWithFlags(&sB, cudaStreamNonBlocking);
    cudaStreamCreateWithFlags(&sC, cudaStreamNonBlocking);
    cudaStreamCreateWithFlags(&sD, cudaStreamNonBlocking);
    cudaEvent_t eF, eA, eB, eC, eD, eW;
    cudaEventCreateWithFlags(&eF, cudaEventDisableTiming);
    cudaEventCreateWithFlags(&eA, cudaEventDisableTiming);
    cudaEventCreateWithFlags(&eB, cudaEventDisableTiming);
    cudaEventCreateWithFlags(&eC, cudaEventDisableTiming);
    cudaEventCreateWithFlags(&eD, cudaEventDisableTiming);
    cudaEventCreateWithFlags(&eW, cudaEventDisableTiming);

    // fork from the (captured) main stream
    cudaEventRecord(eF, 0);
    cudaStreamWaitEvent(sA, eF, 0);
    cudaStreamWaitEvent(sB, eF, 0);
    cudaStreamWaitEvent(sC, eF, 0);
    cudaStreamWaitEvent(sD, eF, 0);

    int n4 = E >> 2;
    int csrGrid = (n4 + 1 + 255) / 256;

    // track A: CSR build
    cudaMemsetAsync(cnt_ptr, 0, (Ndst + 1) * sizeof(int), sA);
    k_count<<<csrGrid, 256, 0, sA>>>(e_dst, E);
    k_scan<<<1, 1024, 0, sA>>>(Ndst);
    k_scatter<<<csrGrid, 256, 0, sA>>>(e_src, e_dst, E);
    cudaEventRecord(eA, sA);

    // track B: wrv (needed by v-GEMM), then attention logits
    k_wrv<<<SDIM, SDIM, 0, sB>>>(W_res, W_pred2, b_pred2);
    cudaEventRecord(eW, sB);
    k_fold_att<<<2, 512, 0, sB>>>(W_src, att_src, W_dst, att_dst);
    dim3 gl((maxN + 7) / 8, 2);
    k_logits<<<gl, 256, 0, sB>>>(x_src, x_dst, Nsrc, Ndst);
    cudaEventRecord(eB, sB);

    // track C: u = x_src @ W_res^T  (bf16 out)
    k_gemm1<<<(Nsrc + TM - 1) / TM, 256, 0, sC>>>(x_src, W_res, nullptr, nullptr, Nsrc, 2);
    cudaEventRecord(eC, sC);

    // track D: out = x_dst @ W_self^T + b_self
    k_gemm1<<<(Ndst + TM - 1) / TM, 256, 0, sD>>>(x_dst, W_self, b_self, out, Ndst, 0);
    cudaEventRecord(eD, sD);

    // main: t1 = relu(x_dst @ W_pred1^T + b1), then v = t1 @ Wrv^T + brv
    k_gemm1<<<(Ndst + TM - 1) / TM, 256>>>(x_dst, W_pred1, b_pred1, t1_ptr, Ndst, 1);
    cudaStreamWaitEvent(0, eW, 0);
    k_gemm1<<<(Ndst + TM - 1) / TM, 256>>>(t1_ptr, wrv_ptr, brv_ptr, v_ptr, Ndst, 0);

    // join everything before the edge kernel
    cudaStreamWaitEvent(0, eA, 0);
    cudaStreamWaitEvent(0, eB, 0);
    cudaStreamWaitEvent(0, eC, 0);
    cudaStreamWaitEvent(0, eD, 0);

    k_edge<<<Ndst, 128>>>(out);

    cudaEventDestroy(eF); cudaEventDestroy(eA); cudaEventDestroy(eB);
    cudaEventDestroy(eC); cudaEventDestroy(eD); cudaEventDestroy(eW);
    cudaStreamDestroy(sA); cudaStreamDestroy(sB);
    cudaStreamDestroy(sC); cudaStreamDestroy(sD);
}

// round 11
// speedup vs baseline: 1.4359x; 1.4359x over previous
#include <cuda_runtime.h>
#include <cuda_bf16.h>

// Problem constants (fixed by dataset)
#define NSRC_MAX 10000
#define NDST_MAX 10000
#define EDGE_MAX 640000
#define SDIM 128
#define HNUM 4
#define DDIM 32

typedef unsigned long long u64;
typedef unsigned int u32;

// ---------------- device scratch (static, no allocs) ----------------
__device__ u32   g_ub[NSRC_MAX * (SDIM / 2)];   // x_src @ W_res^T as bf16x2 pairs
__device__ float g_v[NDST_MAX * SDIM];          // pred  @ W_res^T
__device__ float g_t1[NDST_MAX * SDIM];         // relu(x_dst @ W_pred1^T + b1)
__device__ float g_as[NSRC_MAX * HNUM];
__device__ float g_ad[NDST_MAX * HNUM];
__device__ float g_Msrc[SDIM * HNUM];
__device__ float g_Mdst[SDIM * HNUM];
__device__ float g_Wrv[SDIM * SDIM];            // W_res @ W_pred2
__device__ float g_brv[SDIM];                   // W_res @ b_pred2
__device__ int   g_cnt[NDST_MAX + 1];
__device__ int   g_off[NDST_MAX + 1];
__device__ int   g_cur[NDST_MAX];
__device__ int   g_csr_src[EDGE_MAX];

__device__ __forceinline__ float warp_sum(float v) {
    #pragma unroll
    for (int o = 16; o; o >>= 1) v += __shfl_xor_sync(0xffffffffu, v, o);
    return v;
}

// ---- f32x2 packed-math helpers (FFMA2: PTX-only, doubles fp32 FMA rate) ----
__device__ __forceinline__ u64 pack2(float x, float y) {
    u64 r;
    asm("mov.b64 %0, {%1, %2};" : "=l"(r)
        : "r"(__float_as_uint(x)), "r"(__float_as_uint(y)));
    return r;
}
__device__ __forceinline__ float2 unpack2(u64 v) {
    u32 lo, hi;
    asm("mov.b64 {%0, %1}, %2;" : "=r"(lo), "=r"(hi) : "l"(v));
    return make_float2(__uint_as_float(lo), __uint_as_float(hi));
}
__device__ __forceinline__ void fma2(u64& d, u64 a, u64 b) {
    asm("fma.rn.f32x2 %0, %1, %2, %3;" : "=l"(d) : "l"(a), "l"(b), "l"(d));
}
// pack (lo, hi) floats to bf16x2 (first PTX source -> upper half)
__device__ __forceinline__ u32 bf2(float lo, float hi) {
    u32 r;
    asm("cvt.rn.bf16x2.f32 %0, %1, %2;" : "=r"(r) : "f"(hi), "f"(lo));
    return r;
}

// ---------------- tiny precompute kernels ----------------
// Fold attention vectors into weights: M[s,h] = sum_d W[(h*32+d)*128 + s] * att[h*32+d]
__global__ void k_fold_att(const float* __restrict__ Wsrc, const float* __restrict__ attsrc,
                           const float* __restrict__ Wdst, const float* __restrict__ attdst) {
    int b = blockIdx.x;
    const float* W   = b ? Wdst   : Wsrc;
    const float* att = b ? attdst : attsrc;
    float* out       = b ? g_Mdst : g_Msrc;
    int t = threadIdx.x;
    if (t >= SDIM * HNUM) return;
    int s = t >> 2, h = t & 3;
    float acc = 0.f;
    #pragma unroll 8
    for (int d = 0; d < DDIM; d++)
        acc += W[(h * DDIM + d) * SDIM + s] * att[h * DDIM + d];
    out[s * 4 + h] = acc;
}

// W_rv[o,k] = sum_i W_res[o,i] * W_pred2[i,k];  b_rv[o] = sum_i W_res[o,i] * b_pred2[i]
__global__ void k_wrv(const float* __restrict__ Wres, const float* __restrict__ Wpred2,
                      const float* __restrict__ bpred2) {
    __shared__ float sh[SDIM];
    __shared__ float ws[4];
    int o = blockIdx.x, t = threadIdx.x;
    sh[t] = Wres[o * SDIM + t];
    __syncthreads();
    float s = 0.f;
    #pragma unroll 8
    for (int i = 0; i < SDIM; i++)
        s += sh[i] * Wpred2[i * SDIM + t];
    g_Wrv[o * SDIM + t] = s;
    float p = sh[t] * bpred2[t];
    p = warp_sum(p);
    if ((t & 31) == 0) ws[t >> 5] = p;
    __syncthreads();
    if (t == 0) g_brv[o] = ws[0] + ws[1] + ws[2] + ws[3];
}

// a[n,h] = sum_k x[n,k] * M[k,h]   (warp per row)
__global__ void k_logits(const float* __restrict__ xsrc, const float* __restrict__ xdst,
                         int Nsrc, int Ndst) {
    int y = blockIdx.y;
    const float* x  = y ? xdst   : xsrc;
    const float* Mw = y ? g_Mdst : g_Msrc;
    float* out      = y ? g_ad   : g_as;
    int N           = y ? Ndst   : Nsrc;
    int warp = threadIdx.x >> 5, lane = threadIdx.x & 31;
    int row = blockIdx.x * 8 + warp;
    if (row >= N) return;
    const float* xr = x + row * SDIM;
    float p0 = 0, p1 = 0, p2 = 0, p3 = 0;
    #pragma unroll
    for (int k = lane; k < SDIM; k += 32) {
        float xv = __ldg(&xr[k]);
        p0 += xv * Mw[k * 4 + 0];
        p1 += xv * Mw[k * 4 + 1];
        p2 += xv * Mw[k * 4 + 2];
        p3 += xv * Mw[k * 4 + 3];
    }
    p0 = warp_sum(p0); p1 = warp_sum(p1); p2 = warp_sum(p2); p3 = warp_sum(p3);
    if (lane == 0) {
        out[row * 4 + 0] = p0; out[row * 4 + 1] = p1;
        out[row * 4 + 2] = p2; out[row * 4 + 3] = p3;
    }
}

// ---------------- GEMM: C[M,128] = act(A[M,128] @ B[128,128]^T + bias) ----------------
// 128x128 tile, 256 threads, 8x8 per thread via f32x2 packed FMA.
#define TM 128
#define TN 128
#define TK 16
__global__ __launch_bounds__(256) void k_gemm(
    const float* __restrict__ xsrc, const float* __restrict__ xdst,
    const float* __restrict__ Wres, const float* __restrict__ Wpred1,
    const float* __restrict__ bpred1, const float* __restrict__ Wself,
    const float* __restrict__ bself, float* __restrict__ dout,
    int Nsrc, int Ndst, int phase) {

    const float *A, *B, *bias;
    float* C = nullptr;
    int M;
    int doRelu = 0, toBf16 = 0;
    if (phase == 0) {
        int j = blockIdx.y;
        if (j == 0)      { A = xsrc; B = Wres;   bias = nullptr; M = Nsrc; toBf16 = 1; }
        else if (j == 1) { A = xdst; B = Wpred1; bias = bpred1;  C = g_t1; M = Ndst; doRelu = 1; }
        else             { A = xdst; B = Wself;  bias = bself;   C = dout; M = Ndst; }
    } else {
        A = g_t1; B = g_Wrv; bias = g_brv; C = g_v; M = Ndst;
    }

    __shared__ float As[TK][TM + 4];
    __shared__ float Bs[TK][TN + 4];

    int tid = threadIdx.x;
    int tx = tid & 15, ty = tid >> 4;
    int row0 = blockIdx.x * TM;
    if (row0 >= M) return;

    u64 acc[8][4];
    #pragma unroll
    for (int r = 0; r < 8; r++)
        #pragma unroll
        for (int c = 0; c < 4; c++) acc[r][c] = 0ull;

    for (int k0 = 0; k0 < SDIM; k0 += TK) {
        // A tile: 128 rows x 16 k = 512 float4 loads (2 per thread)
        #pragma unroll
        for (int i = 0; i < 2; i++) {
            int idx = tid + 256 * i;
            int r = idx >> 2, q = idx & 3;
            int grow = row0 + r;
            float4 vv = make_float4(0.f, 0.f, 0.f, 0.f);
            if (grow < M)
                vv = *reinterpret_cast<const float4*>(&A[grow * SDIM + k0 + q * 4]);
            As[q * 4 + 0][r] = vv.x; As[q * 4 + 1][r] = vv.y;
            As[q * 4 + 2][r] = vv.z; As[q * 4 + 3][r] = vv.w;
        }
        // B tile: 128 n x 16 k
        #pragma unroll
        for (int i = 0; i < 2; i++) {
            int idx = tid + 256 * i;
            int n = idx >> 2, q = idx & 3;
            float4 vv = *reinterpret_cast<const float4*>(&B[n * SDIM + k0 + q * 4]);
            Bs[q * 4 + 0][n] = vv.x; Bs[q * 4 + 1][n] = vv.y;
            Bs[q * 4 + 2][n] = vv.z; Bs[q * 4 + 3][n] = vv.w;
        }
        __syncthreads();
        #pragma unroll
        for (int kk = 0; kk < TK; kk++) {
            float4 aL = *reinterpret_cast<const float4*>(&As[kk][ty * 4]);
            float4 aH = *reinterpret_cast<const float4*>(&As[kk][ty * 4 + 64]);
            float4 bL = *reinterpret_cast<const float4*>(&Bs[kk][tx * 4]);
            float4 bH = *reinterpret_cast<const float4*>(&Bs[kk][tx * 4 + 64]);
            u64 a2[8];
            a2[0] = pack2(aL.x, aL.x); a2[1] = pack2(aL.y, aL.y);
            a2[2] = pack2(aL.z, aL.z); a2[3] = pack2(aL.w, aL.w);
            a2[4] = pack2(aH.x, aH.x); a2[5] = pack2(aH.y, aH.y);
            a2[6] = pack2(aH.z, aH.z); a2[7] = pack2(aH.w, aH.w);
            u64 b2[4];
            b2[0] = pack2(bL.x, bL.y); b2[1] = pack2(bL.z, bL.w);
            b2[2] = pack2(bH.x, bH.y); b2[3] = pack2(bH.z, bH.w);
            #pragma unroll
            for (int r = 0; r < 8; r++)
                #pragma unroll
                for (int c = 0; c < 4; c++)
                    fma2(acc[r][c], a2[r], b2[c]);
        }
        __syncthreads();
    }

    // epilogue: columns tx*4..tx*4+3 (lo) and 64+tx*4..+3 (hi)
    float4 bsL = make_float4(0.f, 0.f, 0.f, 0.f), bsH = bsL;
    if (bias) {
        bsL = *reinterpret_cast<const float4*>(&bias[tx * 4]);
        bsH = *reinterpret_cast<const float4*>(&bias[64 + tx * 4]);
    }
    #pragma unroll
    for (int r = 0; r < 8; r++) {
        int grow = row0 + ((r < 4) ? (ty * 4 + r) : (64 + ty * 4 + r - 4));
        if (grow >= M) continue;
        float2 p0 = unpack2(acc[r][0]), p1 = unpack2(acc[r][1]);
        float2 p2 = unpack2(acc[r][2]), p3 = unpack2(acc[r][3]);
        float4 lo = make_float4(p0.x + bsL.x, p0.y + bsL.y, p1.x + bsL.z, p1.y + bsL.w);
        float4 hi = make_float4(p2.x + bsH.x, p2.y + bsH.y, p3.x + bsH.z, p3.y + bsH.w);
        if (doRelu) {
            lo.x = fmaxf(lo.x, 0.f); lo.y = fmaxf(lo.y, 0.f);
            lo.z = fmaxf(lo.z, 0.f); lo.w = fmaxf(lo.w, 0.f);
            hi.x = fmaxf(hi.x, 0.f); hi.y = fmaxf(hi.y, 0.f);
            hi.z = fmaxf(hi.z, 0.f); hi.w = fmaxf(hi.w, 0.f);
        }
        if (toBf16) {
            uint2 uL = make_uint2(bf2(lo.x, lo.y), bf2(lo.z, lo.w));
            uint2 uH = make_uint2(bf2(hi.x, hi.y), bf2(hi.z, hi.w));
            *reinterpret_cast<uint2*>(&g_ub[grow * (SDIM / 2) + tx * 2]) = uL;
            *reinterpret_cast<uint2*>(&g_ub[grow * (SDIM / 2) + 32 + tx * 2]) = uH;
        } else {
            *reinterpret_cast<float4*>(&C[grow * SDIM + tx * 4]) = lo;
            *reinterpret_cast<float4*>(&C[grow * SDIM + 64 + tx * 4]) = hi;
        }
    }
}

// ---------------- CSR build (4 edges / thread for atomic-latency overlap) ----------------
__global__ void k_count(const int* __restrict__ edst, int E) {
    int i = blockIdx.x * blockDim.x + threadIdx.x;
    int n4 = E >> 2;
    if (i < n4) {
        int4 d = reinterpret_cast<const int4*>(edst)[i];
        atomicAdd(&g_cnt[d.x], 1);
        atomicAdd(&g_cnt[d.y], 1);
        atomicAdd(&g_cnt[d.z], 1);
        atomicAdd(&g_cnt[d.w], 1);
    } else if (i == n4) {
        for (int j = n4 * 4; j < E; j++) atomicAdd(&g_cnt[edst[j]], 1);
    }
}

__global__ void k_scan(int N) {
    __shared__ int sh[1024];
    int t = threadIdx.x;
    int per = (N + 1023) >> 10;
    int s = t * per, e = min(N, s + per);
    int tot = 0;
    for (int i = s; i < e; i++) tot += g_cnt[i];
    sh[t] = tot;
    __syncthreads();
    for (int o = 1; o < 1024; o <<= 1) {
        int v = (t >= o) ? sh[t - o] : 0;
        __syncthreads();
        sh[t] += v;
        __syncthreads();
    }
    int run = (t == 0) ? 0 : sh[t - 1];
    for (int i = s; i < e; i++) {
        g_off[i] = run;
        g_cur[i] = run;
        run += g_cnt[i];
    }
    if (t == 1023) g_off[N] = sh[1023];
}

__global__ void k_scatter(const int* __restrict__ esrc, const int* __restrict__ edst, int E) {
    int i = blockIdx.x * blockDim.x + threadIdx.x;
    int n4 = E >> 2;
    if (i < n4) {
        int4 d = reinterpret_cast<const int4*>(edst)[i];
        int4 s = reinterpret_cast<const int4*>(esrc)[i];
        int p0 = atomicAdd(&g_cur[d.x], 1);
        int p1 = atomicAdd(&g_cur[d.y], 1);
        int p2 = atomicAdd(&g_cur[d.z], 1);
        int p3 = atomicAdd(&g_cur[d.w], 1);
        g_csr_src[p0] = s.x;
        g_csr_src[p1] = s.y;
        g_csr_src[p2] = s.z;
        g_csr_src[p3] = s.w;
    } else if (i == n4) {
        for (int j = n4 * 4; j < E; j++) {
            int p = atomicAdd(&g_cur[edst[j]], 1);
            g_csr_src[p] = esrc[j];
        }
    }
}

// ---------------- edge aggregation: one block (128 thr) per dst node ----------------
#define CAP 512
__global__ __launch_bounds__(128) void k_edge(float* __restrict__ dout) {
    __shared__ int    sh_src[CAP];
    __shared__ float  sh_ex[4][CAP];
    __shared__ float  sh_denom[4];
    __shared__ float2 red[64];

    int d = blockIdx.x;
    int t = threadIdx.x;
    int start = g_off[d], end = g_off[d + 1];
    int n = end - start;

    // pass 1: warp h1 computes exp-weights for head h1; warp 0 also caches src ids
    int h1 = t >> 5, lane = t & 31;
    float adh1 = g_ad[d * 4 + h1];
    float part = 0.f;
    for (int i = lane; i < n; i += 32) {
        int src = g_csr_src[start + i];
        if (h1 == 0 && i < CAP) sh_src[i] = src;
        float z = g_as[src * 4 + h1] + adh1;
        z = fmaxf(z, 0.f) + 0.2f * fminf(z, 0.f);   // leaky_relu 0.2
        float ex = __expf(z);                        // softmax shift-invariant: skip amax
        if (i < CAP) sh_ex[h1][i] = ex;
        part += ex;
    }
    part = warp_sum(part);
    if (lane == 0) sh_denom[h1] = part;
    __syncthreads();

    // pass 2: 64 channel-pairs x 2 edge-slots; bf16x2 u loads
    int p = t & 63, slot = t >> 6;
    int h2 = p >> 4;                     // head of channels 2p, 2p+1
    float denom = sh_denom[h2];
    float inv = 1.f / (denom + 1e-16f);
    float sumw = denom * inv;

    float ax = 0.f, ay = 0.f;
    int ncap = n < CAP ? n : CAP;
    #pragma unroll 4
    for (int i = slot; i < ncap; i += 2) {
        int src = sh_src[i];
        float w = sh_ex[h2][i];
        u32 uv = __ldg(&g_ub[src * (SDIM / 2) + p]);
        float ux = __uint_as_float(uv << 16);
        float uy = __uint_as_float(uv & 0xffff0000u);
        ax += w * ux;
        ay += w * uy;
    }
    // overflow path (n > CAP): recompute weights on the fly (rare/never for this data)
    if (n > CAP) {
        float adh2 = g_ad[d * 4 + h2];
        for (int j = CAP + slot; j < n; j += 2) {
            int src = g_csr_src[start + j];
            float z = g_as[src * 4 + h2] + adh2;
            z = fmaxf(z, 0.f) + 0.2f * fminf(z, 0.f);
            float w = __expf(z);
            u32 uv = __ldg(&g_ub[src * (SDIM / 2) + p]);
            ax += w * __uint_as_float(uv << 16);
            ay += w * __uint_as_float(uv & 0xffff0000u);
        }
    }

    if (slot == 1) red[p] = make_float2(ax, ay);
    __syncthreads();
    if (slot == 0) {
        ax += red[p].x;
        ay += red[p].y;
        float2 vv = *reinterpret_cast<const float2*>(&g_v[d * SDIM + 2 * p]);
        float2 oo = *reinterpret_cast<const float2*>(&dout[d * SDIM + 2 * p]);
        oo.x += ax * inv - vv.x * sumw;
        oo.y += ay * inv - vv.y * sumw;
        *reinterpret_cast<float2*>(&dout[d * SDIM + 2 * p]) = oo;
    }
}

// ---------------- launch: R3 topology + fast CSR track ----------------
extern "C" void kernel_launch(void* const* d_in, const int* in_sizes, int n_in,
                              void* d_out, int out_size) {
    const float* x_src   = (const float*)d_in[0];
    const float* x_dst   = (const float*)d_in[1];
    const float* W_pred1 = (const float*)d_in[2];
    const float* b_pred1 = (const float*)d_in[3];
    const float* W_pred2 = (const float*)d_in[4];
    const float* b_pred2 = (const float*)d_in[5];
    const float* W_res   = (const float*)d_in[6];
    const float* W_src   = (const float*)d_in[7];
    const float* W_dst   = (const float*)d_in[8];
    const float* att_src = (const float*)d_in[9];
    const float* att_dst = (const float*)d_in[10];
    const float* W_self  = (const float*)d_in[11];
    const float* b_self  = (const float*)d_in[12];
    const int*   e_src   = (const int*)d_in[13];
    const int*   e_dst   = (const int*)d_in[14];
    float* out = (float*)d_out;

    int Nsrc = in_sizes[0] / SDIM;
    int Ndst = in_sizes[1] / SDIM;
    int E    = in_sizes[13];
    int maxN = Nsrc > Ndst ? Nsrc : Ndst;

    void* cnt_ptr = nullptr;
    cudaGetSymbolAddress(&cnt_ptr, g_cnt);

    cudaStream_t sA, sB;
    cudaStreamCreateWithFlags(&sA, cudaStreamNonBlocking);
    cudaStreamCreateWithFlags(&sB, cudaStreamNonBlocking);
    cudaEvent_t eF, eA, eB;
    cudaEventCreateWithFlags(&eF, cudaEventDisableTiming);
    cudaEventCreateWithFlags(&eA, cudaEventDisableTiming);
    cudaEventCreateWithFlags(&eB, cudaEventDisableTiming);

    // fork from the (captured) main stream
    cudaEventRecord(eF, 0);
    cudaStreamWaitEvent(sA, eF, 0);
    cudaStreamWaitEvent(sB, eF, 0);

    int n4 = E >> 2;
    int csrGrid = (n4 + 1 + 255) / 256;

    // track A: CSR build (independent of all GEMMs)
    cudaMemsetAsync(cnt_ptr, 0, (Ndst + 1) * sizeof(int), sA);
    k_count<<<csrGrid, 256, 0, sA>>>(e_dst, E);
    k_scan<<<1, 1024, 0, sA>>>(Ndst);
    k_scatter<<<csrGrid, 256, 0, sA>>>(e_src, e_dst, E);

    // track B: attention logits
    k_fold_att<<<2, 512, 0, sB>>>(W_src, att_src, W_dst, att_dst);
    dim3 gl((maxN + 7) / 8, 2);
    k_logits<<<gl, 256, 0, sB>>>(x_src, x_dst, Nsrc, Ndst);

    // main: GEMM chain (fused phase-0 fills the chip in one launch)
    k_wrv<<<SDIM, SDIM>>>(W_res, W_pred2, b_pred2);
    dim3 g0((maxN + TM - 1) / TM, 3);
    k_gemm<<<g0, 256>>>(x_src, x_dst, W_res, W_pred1, b_pred1, W_self, b_self,
                        out, Nsrc, Ndst, 0);
    dim3 g1((Ndst + TM - 1) / TM, 1);
    k_gemm<<<g1, 256>>>(x_src, x_dst, W_res, W_pred1, b_pred1, W_self, b_self,
                        out, Nsrc, Ndst, 1);

    // join side tracks back into the main stream
    cudaEventRecord(eA, sA);
    cudaEventRecord(eB, sB);
    cudaStreamWaitEvent(0, eA, 0);
    cudaStreamWaitEvent(0, eB, 0);

    k_edge<<<Ndst, 128>>>(out);

    cudaEventDestroy(eF);
    cudaEventDestroy(eA);
    cudaEventDestroy(eB);
    cudaStreamDestroy(sA);
    cudaStreamDestroy(sB);
}